// round 14
// baseline (speedup 1.0000x reference)
#include <cuda_runtime.h>
#include <cuda_bf16.h>
#include <cuda_fp16.h>
#include <cstdint>

// BaseDenseAttention — causal dense attention, fp32, B=8 T=2048 D=64.
// Outputs concatenated in d_out: weights [B,T,T], result [B,T,D].
// Round 12: overlap reduce's DRAM stream with attn's MMA stream via a
// 4-launch pipeline (deterministic, kernel-boundary dependencies):
//   1) prep   2) attn_big (qt 16-31)
//   3) fused: attn_small (qt 0-15) + reduce of big rows, one grid, 1:7
//      blockIdx interleave so MMA CTAs and DRAM CTAs co-reside per SM
//   4) reduce_small (rows 0-1023).
// Numerics unchanged from R11: 3-term bf16 split S, fp16 PV + online max,
// fp16 E scratch + per-step e^m table, exact reconstruction in reduce.

#define B_  8
#define T_  2048
#define D_  64
#define TM  64
#define TN  128
#define NQT 32                 // 64-row q tiles
#define CHUNK  2

// scratch: partial row sums / partial O per (b,qt64,split<=8)
__device__ float g_pl[2048 * 64];
__device__ float g_pO[2048 * 64 * 64];
// fp16 unnormalized-E scratch (e' = exp(s - m_step)) and per-step e^m table
__device__ uint16_t g_ew[(size_t)B_ * T_ * T_];
__device__ float    g_pm[2048 * 4 * 64];               // [chunk][step][row]

// pre-converted tiles: [tensor(3)][b(8)][tile128(16)][2 planes][128 x 144B]
#define PITCH 144
#define PLANE 18432
#define QPLANE 9216
__device__ __align__(16) char g_cvt[3 * 8 * 16 * 2 * PLANE];

__device__ __forceinline__ char* cvt_plane(int t, int b, int tile) {
    return g_cvt + (size_t)(((t * 8 + b) * 16 + tile) * 2) * PLANE;
}

#define SM_QH 0
#define SM_KH (2 * QPLANE)
#define SM_VH (SM_KH + 2 * PLANE)
#define SMEM_TOTAL (SM_VH + PLANE)      // 73728 B

__device__ __forceinline__ uint32_t smem_u32(const void* p) {
    uint32_t a;
    asm("{ .reg .u64 t; cvta.to.shared.u64 t, %1; cvt.u32.u64 %0, t; }" : "=r"(a) : "l"(p));
    return a;
}
__device__ __forceinline__ void ldsm4(uint32_t addr, uint32_t* r) {
    asm volatile("ldmatrix.sync.aligned.m8n8.x4.shared.b16 {%0,%1,%2,%3}, [%4];"
                 : "=r"(r[0]), "=r"(r[1]), "=r"(r[2]), "=r"(r[3]) : "r"(addr));
}
__device__ __forceinline__ void ldsm4t(uint32_t addr, uint32_t* r) {
    asm volatile("ldmatrix.sync.aligned.m8n8.x4.trans.shared.b16 {%0,%1,%2,%3}, [%4];"
                 : "=r"(r[0]), "=r"(r[1]), "=r"(r[2]), "=r"(r[3]) : "r"(addr));
}
__device__ __forceinline__ void mma16816(float* d, const uint32_t* a, const uint32_t* b) {
    asm volatile("mma.sync.aligned.m16n8k16.row.col.f32.bf16.bf16.f32 "
                 "{%0,%1,%2,%3}, {%4,%5,%6,%7}, {%8,%9}, {%0,%1,%2,%3};"
                 : "+f"(d[0]), "+f"(d[1]), "+f"(d[2]), "+f"(d[3])
                 : "r"(a[0]), "r"(a[1]), "r"(a[2]), "r"(a[3]), "r"(b[0]), "r"(b[1]));
}
__device__ __forceinline__ void mma16816h(float* d, const uint32_t* a, const uint32_t* b) {
    asm volatile("mma.sync.aligned.m16n8k16.row.col.f32.f16.f16.f32 "
                 "{%0,%1,%2,%3}, {%4,%5,%6,%7}, {%8,%9}, {%0,%1,%2,%3};"
                 : "+f"(d[0]), "+f"(d[1]), "+f"(d[2]), "+f"(d[3])
                 : "r"(a[0]), "r"(a[1]), "r"(a[2]), "r"(a[3]), "r"(b[0]), "r"(b[1]));
}
__device__ __forceinline__ void cp16(uint32_t dst, const void* src) {
    asm volatile("cp.async.cg.shared.global [%0], [%1], 16;" :: "r"(dst), "l"(src));
}
#define CP_COMMIT() asm volatile("cp.async.commit_group;" ::: "memory")
#define CP_WAIT(N)  asm volatile("cp.async.wait_group %0;" :: "n"(N) : "memory")

__device__ __forceinline__ void cp_q(uint32_t dst, const char* srchi, int tid) {
    #pragma unroll
    for (int i = 0; i < 9; ++i) {
        int s = tid + i * 128;
        const char* src = (s < 576) ? (srchi + s * 16)
                                    : (srchi + PLANE + (s - 576) * 16);
        cp16(dst + s * 16, src);
    }
}
__device__ __forceinline__ void cp_k(uint32_t dst, const char* src, int tid) {
    #pragma unroll
    for (int i = 0; i < 18; ++i) {
        int o = (tid + i * 128) * 16;
        cp16(dst + o, src + o);
    }
}
__device__ __forceinline__ void cp_v(uint32_t dst, const char* src, int tid) {
    #pragma unroll
    for (int i = 0; i < 9; ++i) {
        int o = (tid + i * 128) * 16;
        cp16(dst + o, src + o);
    }
}

__device__ __forceinline__ void split2(float x, float y, uint32_t& hi, uint32_t& lo) {
    __nv_bfloat16 hx = __float2bfloat16_rn(x);
    __nv_bfloat16 hy = __float2bfloat16_rn(y);
    float rx = x - __bfloat162float(hx);
    float ry = y - __bfloat162float(hy);
    __nv_bfloat16 lx = __float2bfloat16_rn(rx);
    __nv_bfloat16 ly = __float2bfloat16_rn(ry);
    hi = ((uint32_t)__bfloat16_as_ushort(hy) << 16) | __bfloat16_as_ushort(hx);
    lo = ((uint32_t)__bfloat16_as_ushort(ly) << 16) | __bfloat16_as_ushort(lx);
}
__device__ __forceinline__ uint32_t pack_h2(float x, float y) {
    return ((uint32_t)__half_as_ushort(__float2half_rn(y)) << 16)
         | __half_as_ushort(__float2half_rn(x));
}

// big-first chunk schedule over [qlo, qhi]: full 2-tile chunks (qt desc),
// then 1-tile leftovers.
__device__ __forceinline__ void get_chunk(int cid, int qlo, int qhi,
                                          int& qt, int& sp) {
    int c = cid;
    for (int q = qhi; q >= qlo; --q) {
        int f = ((q >> 1) + 1) >> 1;
        if (c < f) { qt = q; sp = c; return; }
        c -= f;
    }
    for (int q = qhi; q >= qlo; --q) {
        int ntk = (q >> 1) + 1;
        if (ntk & 1) {
            if (c == 0) { qt = q; sp = ntk >> 1; return; }
            --c;
        }
    }
    qt = qlo; sp = 0;
}

// ---- prep: fp32 tiles -> bf16 hi/lo (Q,K) or fp16 (V) pitched planes ----
__global__ __launch_bounds__(256)
void prep_kernel(const float* __restrict__ q, const float* __restrict__ k,
                 const float* __restrict__ v)
{
    const int tile = blockIdx.x >> 3, qu = blockIdx.x & 7;   // 16 rows per CTA
    const int b = blockIdx.y, t = blockIdx.z;
    const int tid = threadIdx.x;
    const float* src = (t == 0 ? q : (t == 1 ? k : v))
                       + ((size_t)(b * T_ + tile * 128 + qu * 16)) * D_;
    char* dh = cvt_plane(t, b, tile) + qu * 16 * PITCH;
    char* dl = dh + PLANE;
    int row = tid >> 4, c4 = tid & 15;                       // 256 slots
    float4 x = *(const float4*)(src + row * D_ + c4 * 4);
    if (t < 2) {
        uint32_t h0, l0, h1, l1;
        split2(x.x, x.y, h0, l0);
        split2(x.z, x.w, h1, l1);
        *(uint2*)(dh + row * PITCH + c4 * 8) = make_uint2(h0, h1);
        *(uint2*)(dl + row * PITCH + c4 * 8) = make_uint2(l0, l1);
    } else {
        *(uint2*)(dh + row * PITCH + c4 * 8) =
            make_uint2(pack_h2(x.x, x.y), pack_h2(x.z, x.w));
    }
}

// ---- reduce 4 rows (r0..r0+3) of batch b with 128 threads ----
__device__ void reduce4(float* __restrict__ wts, float* __restrict__ res,
                        int b, int r0, int t, int write_w)
{
    float il[4];
    #pragma unroll
    for (int j = 0; j < 4; ++j) {
        int r = r0 + j;
        int qt = r >> 6, rloc = r & 63;
        int ns = (((qt >> 1) + 1) + 1) >> 1;
        int cb = (b * NQT + qt) * 8;
        float l = 0.f;
        #pragma unroll 4
        for (int s = 0; s < ns; ++s) l += g_pl[(cb + s) * 64 + rloc];
        il[j] = 1.f / l;
    }
    if (t < 64) {
        #pragma unroll
        for (int j = 0; j < 4; ++j) {
            int r = r0 + j;
            int qt = r >> 6, rloc = r & 63;
            int ns = (((qt >> 1) + 1) + 1) >> 1;
            int cb = (b * NQT + qt) * 8;
            float acc = 0.f;
            #pragma unroll 4
            for (int s = 0; s < ns; ++s)
                acc += g_pO[(size_t)(cb + s) * 4096 + rloc * 64 + t];
            res[((size_t)(b * T_ + r)) * D_ + t] = acc * il[j];
        }
    }
    if (write_w) {
        uint2 hv[4][4];
        float em[4][4];
        bool  act[4][4];
        #pragma unroll
        for (int j = 0; j < 4; ++j) {
            int r = r0 + j;
            int qt = r >> 6, rloc = r & 63;
            int cb = (b * NQT + qt) * 8;
            const uint16_t* erow = g_ew + ((size_t)(b * T_ + r)) * T_;
            #pragma unroll
            for (int u = 0; u < 4; ++u) {
                int i = t + u * 128;
                act[j][u] = (i * 4 <= r);
                if (act[j][u]) {
                    hv[j][u] = __ldcg((const uint2*)(erow + i * 4));
                    int h = i >> 4;
                    em[j][u] = g_pm[((cb + (h >> 2)) * 4 + (h & 3)) * 64 + rloc];
                }
            }
        }
        #pragma unroll
        for (int j = 0; j < 4; ++j) {
            int r = r0 + j;
            float4* wrow = (float4*)(wts + ((size_t)(b * T_ + r)) * T_);
            #pragma unroll
            for (int u = 0; u < 4; ++u) {
                int i = t + u * 128;
                float4 o = make_float4(0.f, 0.f, 0.f, 0.f);
                if (act[j][u]) {
                    float sc = em[j][u] * il[j];
                    float2 f0 = __half22float2(*(__half2*)&hv[j][u].x);
                    float2 f1 = __half22float2(*(__half2*)&hv[j][u].y);
                    o = make_float4(f0.x * sc, f0.y * sc, f1.x * sc, f1.y * sc);
                }
                __stcs(wrow + i, o);
            }
        }
    }
}

// ---- attn (+ optional fused reduce role) ----
// grid = nattn (spread every `every` blocks) + reduce CTAs (4 big rows each)
__global__ __launch_bounds__(128, 2)
void attn_mma(float* __restrict__ wts, float* __restrict__ res, int write_w,
              int qlo, int qhi, int nattn, int every)
{
    extern __shared__ char smem[];
    const int bx = blockIdx.x;
    const int aslot = bx / every;
    const bool isattn = ((bx % every) == 0) && (aslot < nattn);
    if (!isattn) {
        // reduce role: big rows 1024..2047, 4 per CTA
        const int rid = bx - min(aslot + 1, nattn);
        const int bb = rid >> 8;                  // 256 reduce CTAs per batch
        const int r0 = 1024 + (rid & 255) * 4;
        reduce4(wts, res, bb, r0, threadIdx.x, write_w);
        return;
    }

    const uint32_t sb = smem_u32(smem);
    const int tid  = threadIdx.x;
    const int w    = tid >> 5;
    const int lane = tid & 31;
    const int gid  = lane >> 2;
    const int tig  = lane & 3;
    const int m    = lane >> 3;
    const int rL   = lane & 7;

    const int cid = aslot >> 3;
    const int b   = aslot & 7;
    int qt, sp;
    get_chunk(cid, qlo, qhi, qt, sp);
    const int ntk   = (qt >> 1) + 1;
    const int kt0   = sp * CHUNK;
    const int ktend = min(kt0 + CHUNK, ntk);
    const int dtile = qt >> 1;
    const int chunkid = (b * NQT + qt) * 8 + sp;
    const int rloc  = w * 16 + gid;

    const char* qsrc = cvt_plane(0, b, qt >> 1) + (qt & 1) * 64 * PITCH;
    cp_q(sb + SM_QH, qsrc, tid);                        CP_COMMIT();
    cp_k(sb + SM_KH, cvt_plane(1, b, kt0), tid);        CP_COMMIT();
    cp_v(sb + SM_VH, cvt_plane(2, b, kt0), tid);        CP_COMMIT();

    const uint32_t a_row = (uint32_t)(w * 16 + (m & 1) * 8 + rL);
    const uint32_t a_mo  = (uint32_t)((m >> 1) * 16);
    const uint32_t b_ro  = (uint32_t)((m >> 1) * 8 + rL);
    const uint32_t b_mo  = (uint32_t)((m & 1) * 16);
    const uint32_t v_ro  = (uint32_t)((m & 1) * 8 + rL);
    const uint32_t v_mo  = (uint32_t)((m >> 1) * 16);

    CP_WAIT(2);
    __syncthreads();
    uint32_t qH[4][4], qL[4][4];
    #pragma unroll
    for (int ks = 0; ks < 4; ++ks) {
        uint32_t aaddr = a_row * PITCH + (uint32_t)(ks * 32) + a_mo;
        ldsm4(sb + SM_QH + aaddr, qH[ks]);
        ldsm4(sb + SM_QH + QPLANE + aaddr, qL[ks]);
    }

    float O[8][4];
    #pragma unroll
    for (int i = 0; i < 8; ++i)
        #pragma unroll
        for (int j = 0; j < 4; ++j) O[i][j] = 0.f;
    float sumA = 0.f, sumB = 0.f;
    float mA = -1e30f, mB = -1e30f;
    const int row0 = qt * TM + w * 16 + gid;

    for (int kt = kt0; kt < ktend; ++kt) {
        const int diag = (kt == dtile);
        const int havenext = (kt + 1 < ktend);

        CP_WAIT(1);
        __syncthreads();

        #pragma unroll
        for (int half = 0; half < 2; ++half) {
            const bool skip = diag && (half == 1) && !(qt & 1);

            float S[8][4];
            if (!skip) {
                #pragma unroll
                for (int i = 0; i < 8; ++i)
                    #pragma unroll
                    for (int j = 0; j < 4; ++j) S[i][j] = 0.f;
                #pragma unroll
                for (int ks = 0; ks < 4; ++ks) {
                    #pragma unroll
                    for (int nbp = 0; nbp < 4; ++nbp) {
                        uint32_t bH[4], bL[4];
                        uint32_t krow = (uint32_t)(half * 64 + nbp * 16) + b_ro;
                        uint32_t kaddr = krow * PITCH + (uint32_t)(ks * 32) + b_mo;
                        ldsm4(sb + SM_KH + kaddr, bH);
                        ldsm4(sb + SM_KH + PLANE + kaddr, bL);
                        mma16816(S[2*nbp],   qH[ks], bH);
                        mma16816(S[2*nbp],   qH[ks], bL);
                        mma16816(S[2*nbp],   qL[ks], bH);
                        mma16816(S[2*nbp+1], qH[ks], bH + 2);
                        mma16816(S[2*nbp+1], qH[ks], bL + 2);
                        mma16816(S[2*nbp+1], qL[ks], bH + 2);
                    }
                }
            }

            if (half == 1) {
                __syncthreads();
                if (havenext) { cp_k(sb + SM_KH, cvt_plane(1, b, kt + 1), tid); }
                CP_COMMIT();
            }

            uint32_t E2[8][2];
            if (!skip) {
                const int colbase = kt * TN + half * 64;
                float mlA = -1e30f, mlB = -1e30f;
                #pragma unroll
                for (int nb = 0; nb < 8; ++nb) {
                    int c = colbase + nb * 8 + 2 * tig;
                    if (diag) {
                        if (c     > row0)     S[nb][0] = -1e30f;
                        if (c + 1 > row0)     S[nb][1] = -1e30f;
                        if (c     > row0 + 8) S[nb][2] = -1e30f;
                        if (c + 1 > row0 + 8) S[nb][3] = -1e30f;
                    }
                    mlA = fmaxf(mlA, fmaxf(S[nb][0], S[nb][1]));
                    mlB = fmaxf(mlB, fmaxf(S[nb][2], S[nb][3]));
                }
                mlA = fmaxf(mlA, __shfl_xor_sync(0xFFFFFFFFu, mlA, 1));
                mlA = fmaxf(mlA, __shfl_xor_sync(0xFFFFFFFFu, mlA, 2));
                mlB = fmaxf(mlB, __shfl_xor_sync(0xFFFFFFFFu, mlB, 1));
                mlB = fmaxf(mlB, __shfl_xor_sync(0xFFFFFFFFu, mlB, 2));
                {
                    float mAn = fmaxf(mA, mlA), mBn = fmaxf(mB, mlB);
                    float fA = __expf(mA - mAn), fB = __expf(mB - mBn);
                    mA = mAn; mB = mBn;
                    sumA *= fA; sumB *= fB;
                    #pragma unroll
                    for (int nd = 0; nd < 8; ++nd) {
                        O[nd][0] *= fA; O[nd][1] *= fA;
                        O[nd][2] *= fB; O[nd][3] *= fB;
                    }
                }

                if (write_w && tig == 0) {
                    const int step = (kt - kt0) * 2 + half;
                    g_pm[(chunkid * 4 + step) * 64 + rloc]     = __expf(mA);
                    g_pm[(chunkid * 4 + step) * 64 + rloc + 8] = __expf(mB);
                }

                #pragma unroll
                for (int nb = 0; nb < 8; ++nb) {
                    int c = colbase + nb * 8 + 2 * tig;
                    float e0 = __expf(S[nb][0] - mA);
                    float e1 = __expf(S[nb][1] - mA);
                    float e2 = __expf(S[nb][2] - mB);
                    float e3 = __expf(S[nb][3] - mB);
                    sumA += e0 + e1;
                    sumB += e2 + e3;
                    E2[nb][0] = pack_h2(e0, e1);
                    E2[nb][1] = pack_h2(e2, e3);
                    if (write_w) {
                        *(uint32_t*)&g_ew[((size_t)(b * T_ + row0))     * T_ + c] = E2[nb][0];
                        *(uint32_t*)&g_ew[((size_t)(b * T_ + row0 + 8)) * T_ + c] = E2[nb][1];
                    }
                }
            }

            if (half == 0) {
                CP_WAIT(0);
                __syncthreads();
            }

            if (!skip) {
                #pragma unroll
                for (int pks = 0; pks < 4; ++pks) {
                    uint32_t aP[4] = {E2[2*pks][0], E2[2*pks][1],
                                      E2[2*pks+1][0], E2[2*pks+1][1]};
                    #pragma unroll
                    for (int dbp = 0; dbp < 4; ++dbp) {
                        uint32_t bh[4];
                        uint32_t vrow = (uint32_t)(half * 64 + pks * 16) + v_ro;
                        uint32_t vaddr = vrow * PITCH + (uint32_t)(dbp * 32) + v_mo;
                        ldsm4t(sb + SM_VH + vaddr, bh);
                        mma16816h(O[2*dbp],   aP, bh);
                        mma16816h(O[2*dbp+1], aP, bh + 2);
                    }
                }
            }
        }

        __syncthreads();
        if (havenext) { cp_v(sb + SM_VH, cvt_plane(2, b, kt + 1), tid); }
        CP_COMMIT();
    }

    // ---------- write raw partials ----------
    sumA += __shfl_xor_sync(0xFFFFFFFFu, sumA, 1);
    sumA += __shfl_xor_sync(0xFFFFFFFFu, sumA, 2);
    sumB += __shfl_xor_sync(0xFFFFFFFFu, sumB, 1);
    sumB += __shfl_xor_sync(0xFFFFFFFFu, sumB, 2);
    const float emA = __expf(mA), emB = __expf(mB);
    if (tig == 0) {
        g_pl[chunkid * 64 + rloc]     = sumA * emA;
        g_pl[chunkid * 64 + rloc + 8] = sumB * emB;
    }
    #pragma unroll
    for (int nd = 0; nd < 8; ++nd) {
        int c = nd * 8 + 2 * tig;
        *(float2*)&g_pO[(size_t)chunkid * 4096 + rloc * 64 + c] =
            make_float2(O[nd][0] * emA, O[nd][1] * emA);
        *(float2*)&g_pO[(size_t)chunkid * 4096 + (rloc + 8) * 64 + c] =
            make_float2(O[nd][2] * emB, O[nd][3] * emB);
    }
}

// ---- reduce_small: rows 0..1023 of each batch, 4 rows per 128-thr CTA ----
__global__ __launch_bounds__(128)
void reduce_small(float* __restrict__ wts, float* __restrict__ res, int write_w)
{
    const int b  = blockIdx.x >> 8;            // 256 CTAs per batch
    const int r0 = (blockIdx.x & 255) * 4;     // rows 0..1023
    reduce4(wts, res, b, r0, threadIdx.x, write_w);
}

extern "C" void kernel_launch(void* const* d_in, const int* in_sizes, int n_in,
                              void* d_out, int out_size)
{
    // reference signature order: q, v, k, q_mask, v_mask
    const float* q = (const float*)d_in[0];
    const float* v = (const float*)d_in[1];
    const float* k = (const float*)d_in[2];

    const size_t nW = (size_t)B_ * T_ * T_;
    const size_t nR = (size_t)B_ * T_ * D_;
    const int write_w = ((size_t)out_size >= nW + nR) ? 1 : 0;

    float* wts = (float*)d_out;
    float* res = (float*)d_out + ((size_t)out_size - nR);

    cudaFuncSetAttribute(attn_mma, cudaFuncAttributeMaxDynamicSharedMemorySize, SMEM_TOTAL);

    dim3 pgrid(16 * 8, B_, 3);
    prep_kernel<<<pgrid, 256>>>(q, k, v);
    // attn_big: qt 16..31 -> 104 chunks/batch * 8 = 832 CTAs, all attn
    attn_mma<<<832, 128, SMEM_TOTAL>>>(wts, res, write_w, 16, 31, 832, 1);
    // fused: attn_small (qt 0..15 -> 40*8 = 320) + reduce of big rows
    // (8*1024 rows / 4 = 2048 CTAs); grid 2368, attn every 7th block
    attn_mma<<<2368, 128, SMEM_TOTAL>>>(wts, res, write_w, 0, 15, 320, 7);
    // reduce_small: rows 0..1023 (data from fused kernel's attn part)
    reduce_small<<<2048, 128>>>(wts, res, write_w);
}

// round 15
// speedup vs baseline: 1.3880x; 1.3880x over previous
#include <cuda_runtime.h>
#include <cuda_bf16.h>
#include <cuda_fp16.h>
#include <cstdint>

// BaseDenseAttention — causal dense attention, fp32, B=8 T=2048 D=64.
// Outputs concatenated in d_out: weights [B,T,T], result [B,T,D].
// Round 13: R9 kernels (best: TM=64, 2 CTA/SM, 3-term bf16 S, fp16 PV,
// online max, split-K, fp32 E written straight to wts) + cross-stream
// overlap: attn_big -> {reduce_big on stream2 || attn_small} -> reduce_small.
// Kernel-granularity concurrency avoids R12's fused-role smem trap.

#define B_  8
#define T_  2048
#define D_  64
#define TM  64
#define TN  128
#define NQT 32                 // 64-row q tiles
#define CHUNK  2

// scratch: partial row sums / partial O per (b,qt64,split<=8)
__device__ float g_pl[2048 * 64];
__device__ float g_pO[2048 * 64 * 64];

// pre-converted tiles: [tensor(3)][b(8)][tile128(16)][2 planes][128 x 144B]
// Q,K: plane0 = bf16 hi, plane1 = bf16 lo.  V: plane0 = fp16.
#define PITCH 144
#define PLANE 18432
#define QPLANE 9216
__device__ __align__(16) char g_cvt[3 * 8 * 16 * 2 * PLANE];

__device__ __forceinline__ char* cvt_plane(int t, int b, int tile) {
    return g_cvt + (size_t)(((t * 8 + b) * 16 + tile) * 2) * PLANE;
}

#define SM_QH 0
#define SM_KH (2 * QPLANE)
#define SM_VH (SM_KH + 2 * PLANE)
#define SMEM_TOTAL (SM_VH + PLANE)      // 73728 B

__device__ __forceinline__ uint32_t smem_u32(const void* p) {
    uint32_t a;
    asm("{ .reg .u64 t; cvta.to.shared.u64 t, %1; cvt.u32.u64 %0, t; }" : "=r"(a) : "l"(p));
    return a;
}
__device__ __forceinline__ void ldsm4(uint32_t addr, uint32_t* r) {
    asm volatile("ldmatrix.sync.aligned.m8n8.x4.shared.b16 {%0,%1,%2,%3}, [%4];"
                 : "=r"(r[0]), "=r"(r[1]), "=r"(r[2]), "=r"(r[3]) : "r"(addr));
}
__device__ __forceinline__ void ldsm4t(uint32_t addr, uint32_t* r) {
    asm volatile("ldmatrix.sync.aligned.m8n8.x4.trans.shared.b16 {%0,%1,%2,%3}, [%4];"
                 : "=r"(r[0]), "=r"(r[1]), "=r"(r[2]), "=r"(r[3]) : "r"(addr));
}
__device__ __forceinline__ void mma16816(float* d, const uint32_t* a, const uint32_t* b) {
    asm volatile("mma.sync.aligned.m16n8k16.row.col.f32.bf16.bf16.f32 "
                 "{%0,%1,%2,%3}, {%4,%5,%6,%7}, {%8,%9}, {%0,%1,%2,%3};"
                 : "+f"(d[0]), "+f"(d[1]), "+f"(d[2]), "+f"(d[3])
                 : "r"(a[0]), "r"(a[1]), "r"(a[2]), "r"(a[3]), "r"(b[0]), "r"(b[1]));
}
__device__ __forceinline__ void mma16816h(float* d, const uint32_t* a, const uint32_t* b) {
    asm volatile("mma.sync.aligned.m16n8k16.row.col.f32.f16.f16.f32 "
                 "{%0,%1,%2,%3}, {%4,%5,%6,%7}, {%8,%9}, {%0,%1,%2,%3};"
                 : "+f"(d[0]), "+f"(d[1]), "+f"(d[2]), "+f"(d[3])
                 : "r"(a[0]), "r"(a[1]), "r"(a[2]), "r"(a[3]), "r"(b[0]), "r"(b[1]));
}
__device__ __forceinline__ void cp16(uint32_t dst, const void* src) {
    asm volatile("cp.async.cg.shared.global [%0], [%1], 16;" :: "r"(dst), "l"(src));
}
#define CP_COMMIT() asm volatile("cp.async.commit_group;" ::: "memory")
#define CP_WAIT(N)  asm volatile("cp.async.wait_group %0;" :: "n"(N) : "memory")

__device__ __forceinline__ void cp_q(uint32_t dst, const char* srchi, int tid) {
    #pragma unroll
    for (int i = 0; i < 9; ++i) {
        int s = tid + i * 128;
        const char* src = (s < 576) ? (srchi + s * 16)
                                    : (srchi + PLANE + (s - 576) * 16);
        cp16(dst + s * 16, src);
    }
}
__device__ __forceinline__ void cp_k(uint32_t dst, const char* src, int tid) {
    #pragma unroll
    for (int i = 0; i < 18; ++i) {
        int o = (tid + i * 128) * 16;
        cp16(dst + o, src + o);
    }
}
__device__ __forceinline__ void cp_v(uint32_t dst, const char* src, int tid) {
    #pragma unroll
    for (int i = 0; i < 9; ++i) {
        int o = (tid + i * 128) * 16;
        cp16(dst + o, src + o);
    }
}

__device__ __forceinline__ void split2(float x, float y, uint32_t& hi, uint32_t& lo) {
    __nv_bfloat16 hx = __float2bfloat16_rn(x);
    __nv_bfloat16 hy = __float2bfloat16_rn(y);
    float rx = x - __bfloat162float(hx);
    float ry = y - __bfloat162float(hy);
    __nv_bfloat16 lx = __float2bfloat16_rn(rx);
    __nv_bfloat16 ly = __float2bfloat16_rn(ry);
    hi = ((uint32_t)__bfloat16_as_ushort(hy) << 16) | __bfloat16_as_ushort(hx);
    lo = ((uint32_t)__bfloat16_as_ushort(ly) << 16) | __bfloat16_as_ushort(lx);
}
__device__ __forceinline__ uint32_t pack_h2(float x, float y) {
    return ((uint32_t)__half_as_ushort(__float2half_rn(y)) << 16)
         | __half_as_ushort(__float2half_rn(x));
}

// big-first chunk schedule over [qlo, qhi]: full 2-tile chunks (qt desc),
// then 1-tile leftovers.
__device__ __forceinline__ void get_chunk(int cid, int qlo, int qhi,
                                          int& qt, int& sp) {
    int c = cid;
    for (int q = qhi; q >= qlo; --q) {
        int f = ((q >> 1) + 1) >> 1;
        if (c < f) { qt = q; sp = c; return; }
        c -= f;
    }
    for (int q = qhi; q >= qlo; --q) {
        int ntk = (q >> 1) + 1;
        if (ntk & 1) {
            if (c == 0) { qt = q; sp = ntk >> 1; return; }
            --c;
        }
    }
    qt = qlo; sp = 0;
}

// ---- prep: fp32 tiles -> bf16 hi/lo (Q,K) or fp16 (V) pitched planes ----
__global__ __launch_bounds__(256)
void prep_kernel(const float* __restrict__ q, const float* __restrict__ k,
                 const float* __restrict__ v)
{
    const int tile = blockIdx.x >> 3, qu = blockIdx.x & 7;   // 16 rows per CTA
    const int b = blockIdx.y, t = blockIdx.z;
    const int tid = threadIdx.x;
    const float* src = (t == 0 ? q : (t == 1 ? k : v))
                       + ((size_t)(b * T_ + tile * 128 + qu * 16)) * D_;
    char* dh = cvt_plane(t, b, tile) + qu * 16 * PITCH;
    char* dl = dh + PLANE;
    int row = tid >> 4, c4 = tid & 15;                       // 256 slots
    float4 x = *(const float4*)(src + row * D_ + c4 * 4);
    if (t < 2) {
        uint32_t h0, l0, h1, l1;
        split2(x.x, x.y, h0, l0);
        split2(x.z, x.w, h1, l1);
        *(uint2*)(dh + row * PITCH + c4 * 8) = make_uint2(h0, h1);
        *(uint2*)(dl + row * PITCH + c4 * 8) = make_uint2(l0, l1);
    } else {
        *(uint2*)(dh + row * PITCH + c4 * 8) =
            make_uint2(pack_h2(x.x, x.y), pack_h2(x.z, x.w));
    }
}

__global__ __launch_bounds__(128, 2)
void attn_mma(float* __restrict__ wts, int write_w, int qlo, int qhi)
{
    extern __shared__ char smem[];
    const uint32_t sb = smem_u32(smem);
    const int tid  = threadIdx.x;
    const int w    = tid >> 5;          // 0..3
    const int lane = tid & 31;
    const int gid  = lane >> 2;
    const int tig  = lane & 3;
    const int m    = lane >> 3;
    const int rL   = lane & 7;

    const int cid = blockIdx.x >> 3;
    const int b   = blockIdx.x & 7;
    int qt, sp;
    get_chunk(cid, qlo, qhi, qt, sp);
    const int ntk   = (qt >> 1) + 1;
    const int kt0   = sp * CHUNK;
    const int ktend = min(kt0 + CHUNK, ntk);
    const int dtile = qt >> 1;          // diagonal key-tile index
    const int chunkid = (b * NQT + qt) * 8 + sp;
    const int rloc  = w * 16 + gid;     // 0..63

    // Q source: 64-row half of the 128-row converted tile
    const char* qsrc = cvt_plane(0, b, qt >> 1) + (qt & 1) * 64 * PITCH;
    cp_q(sb + SM_QH, qsrc, tid);                        CP_COMMIT();
    cp_k(sb + SM_KH, cvt_plane(1, b, kt0), tid);        CP_COMMIT();
    cp_v(sb + SM_VH, cvt_plane(2, b, kt0), tid);        CP_COMMIT();

    const uint32_t a_row = (uint32_t)(w * 16 + (m & 1) * 8 + rL);
    const uint32_t a_mo  = (uint32_t)((m >> 1) * 16);
    const uint32_t b_ro  = (uint32_t)((m >> 1) * 8 + rL);
    const uint32_t b_mo  = (uint32_t)((m & 1) * 16);
    const uint32_t v_ro  = (uint32_t)((m & 1) * 8 + rL);
    const uint32_t v_mo  = (uint32_t)((m >> 1) * 16);

    CP_WAIT(2);
    __syncthreads();
    uint32_t qH[4][4], qL[4][4];
    #pragma unroll
    for (int ks = 0; ks < 4; ++ks) {
        uint32_t aaddr = a_row * PITCH + (uint32_t)(ks * 32) + a_mo;
        ldsm4(sb + SM_QH + aaddr, qH[ks]);
        ldsm4(sb + SM_QH + QPLANE + aaddr, qL[ks]);
    }

    float O[8][4];
    #pragma unroll
    for (int i = 0; i < 8; ++i)
        #pragma unroll
        for (int j = 0; j < 4; ++j) O[i][j] = 0.f;
    float sumA = 0.f, sumB = 0.f;
    float mA = -1e30f, mB = -1e30f;
    const int row0 = qt * TM + w * 16 + gid;

    for (int kt = kt0; kt < ktend; ++kt) {
        const int diag = (kt == dtile);
        const int havenext = (kt + 1 < ktend);

        CP_WAIT(1);
        __syncthreads();

        #pragma unroll
        for (int half = 0; half < 2; ++half) {
            // even-qt diagonal tile: upper 64-key half fully masked -> skip
            const bool skip = diag && (half == 1) && !(qt & 1);

            float S[8][4];
            if (!skip) {
                #pragma unroll
                for (int i = 0; i < 8; ++i)
                    #pragma unroll
                    for (int j = 0; j < 4; ++j) S[i][j] = 0.f;
                #pragma unroll
                for (int ks = 0; ks < 4; ++ks) {
                    #pragma unroll
                    for (int nbp = 0; nbp < 4; ++nbp) {
                        uint32_t bH[4], bL[4];
                        uint32_t krow = (uint32_t)(half * 64 + nbp * 16) + b_ro;
                        uint32_t kaddr = krow * PITCH + (uint32_t)(ks * 32) + b_mo;
                        ldsm4(sb + SM_KH + kaddr, bH);
                        ldsm4(sb + SM_KH + PLANE + kaddr, bL);
                        mma16816(S[2*nbp],   qH[ks], bH);
                        mma16816(S[2*nbp],   qH[ks], bL);
                        mma16816(S[2*nbp],   qL[ks], bH);
                        mma16816(S[2*nbp+1], qH[ks], bH + 2);
                        mma16816(S[2*nbp+1], qH[ks], bL + 2);
                        mma16816(S[2*nbp+1], qL[ks], bH + 2);
                    }
                }
            }

            if (half == 1) {
                __syncthreads();
                if (havenext) { cp_k(sb + SM_KH, cvt_plane(1, b, kt + 1), tid); }
                CP_COMMIT();
            }

            uint32_t E2[8][2];
            if (!skip) {
                // ---------- epilogue: mask, online max, exp, store E ----------
                const int colbase = kt * TN + half * 64;
                float mlA = -1e30f, mlB = -1e30f;
                #pragma unroll
                for (int nb = 0; nb < 8; ++nb) {
                    int c = colbase + nb * 8 + 2 * tig;
                    if (diag) {
                        if (c     > row0)     S[nb][0] = -1e30f;
                        if (c + 1 > row0)     S[nb][1] = -1e30f;
                        if (c     > row0 + 8) S[nb][2] = -1e30f;
                        if (c + 1 > row0 + 8) S[nb][3] = -1e30f;
                    }
                    mlA = fmaxf(mlA, fmaxf(S[nb][0], S[nb][1]));
                    mlB = fmaxf(mlB, fmaxf(S[nb][2], S[nb][3]));
                }
                mlA = fmaxf(mlA, __shfl_xor_sync(0xFFFFFFFFu, mlA, 1));
                mlA = fmaxf(mlA, __shfl_xor_sync(0xFFFFFFFFu, mlA, 2));
                mlB = fmaxf(mlB, __shfl_xor_sync(0xFFFFFFFFu, mlB, 1));
                mlB = fmaxf(mlB, __shfl_xor_sync(0xFFFFFFFFu, mlB, 2));
                {
                    float mAn = fmaxf(mA, mlA), mBn = fmaxf(mB, mlB);
                    float fA = __expf(mA - mAn), fB = __expf(mB - mBn);
                    mA = mAn; mB = mBn;
                    sumA *= fA; sumB *= fB;
                    #pragma unroll
                    for (int nd = 0; nd < 8; ++nd) {
                        O[nd][0] *= fA; O[nd][1] *= fA;
                        O[nd][2] *= fB; O[nd][3] *= fB;
                    }
                }
                const float emA = __expf(mA), emB = __expf(mB);
                #pragma unroll
                for (int nb = 0; nb < 8; ++nb) {
                    int c = colbase + nb * 8 + 2 * tig;
                    float e0 = __expf(S[nb][0] - mA);
                    float e1 = __expf(S[nb][1] - mA);
                    float e2 = __expf(S[nb][2] - mB);
                    float e3 = __expf(S[nb][3] - mB);
                    sumA += e0 + e1;
                    sumB += e2 + e3;
                    if (write_w) {
                        *(float2*)(wts + ((size_t)(b * T_ + row0))     * T_ + c) =
                            make_float2(e0 * emA, e1 * emA);
                        *(float2*)(wts + ((size_t)(b * T_ + row0 + 8)) * T_ + c) =
                            make_float2(e2 * emB, e3 * emB);
                    }
                    E2[nb][0] = pack_h2(e0, e1);
                    E2[nb][1] = pack_h2(e2, e3);
                }
            }

            if (half == 0) {
                CP_WAIT(0);
                __syncthreads();
            }

            if (!skip) {
                // ---------- O' += E' @ V (single fp16 term) ----------
                #pragma unroll
                for (int pks = 0; pks < 4; ++pks) {
                    uint32_t aP[4] = {E2[2*pks][0], E2[2*pks][1],
                                      E2[2*pks+1][0], E2[2*pks+1][1]};
                    #pragma unroll
                    for (int dbp = 0; dbp < 4; ++dbp) {
                        uint32_t bh[4];
                        uint32_t vrow = (uint32_t)(half * 64 + pks * 16) + v_ro;
                        uint32_t vaddr = vrow * PITCH + (uint32_t)(dbp * 32) + v_mo;
                        ldsm4t(sb + SM_VH + vaddr, bh);
                        mma16816h(O[2*dbp],   aP, bh);
                        mma16816h(O[2*dbp+1], aP, bh + 2);
                    }
                }
            }
        }

        __syncthreads();
        if (havenext) { cp_v(sb + SM_VH, cvt_plane(2, b, kt + 1), tid); }
        CP_COMMIT();
    }

    // ---------- write raw partials ----------
    sumA += __shfl_xor_sync(0xFFFFFFFFu, sumA, 1);
    sumA += __shfl_xor_sync(0xFFFFFFFFu, sumA, 2);
    sumB += __shfl_xor_sync(0xFFFFFFFFu, sumB, 1);
    sumB += __shfl_xor_sync(0xFFFFFFFFu, sumB, 2);
    const float emA = __expf(mA), emB = __expf(mB);
    if (tig == 0) {
        g_pl[chunkid * 64 + rloc]     = sumA * emA;
        g_pl[chunkid * 64 + rloc + 8] = sumB * emB;
    }
    #pragma unroll
    for (int nd = 0; nd < 8; ++nd) {
        int c = nd * 8 + 2 * tig;
        *(float2*)&g_pO[(size_t)chunkid * 4096 + rloc * 64 + c] =
            make_float2(O[nd][0] * emA, O[nd][1] * emA);
        *(float2*)&g_pO[(size_t)chunkid * 4096 + (rloc + 8) * 64 + c] =
            make_float2(O[nd][2] * emB, O[nd][3] * emB);
    }
}

// ---- reduce rows [rowbase, rowbase+1024) per batch: combine partials,
//      normalize lower triangle, zero upper. 2 rows per 256-thr CTA. ----
__global__ __launch_bounds__(256)
void reduce_kernel(float* __restrict__ wts, float* __restrict__ res,
                   int write_w, int rowbase)
{
    const int tid  = threadIdx.x;
    const int rsel = tid >> 7;             // 0/1
    const int t    = tid & 127;
    const int b    = blockIdx.x >> 9;      // 512 CTAs per batch
    const int r    = rowbase + ((blockIdx.x & 511) << 1) + rsel;
    const int row  = b * T_ + r;
    const int qt   = r >> 6;               // 64-row tile
    const int rloc = r & 63;
    const int ntk  = (qt >> 1) + 1;
    const int ns   = (ntk + 1) >> 1;
    const int cb   = (b * NQT + qt) * 8;

    float l = 0.f;
    #pragma unroll 4
    for (int s = 0; s < ns; ++s) l += g_pl[(cb + s) * 64 + rloc];
    const float il = 1.f / l;

    if (t < 64) {
        float acc = 0.f;
        #pragma unroll 4
        for (int s = 0; s < ns; ++s)
            acc += g_pO[(size_t)(cb + s) * 4096 + rloc * 64 + t];
        res[(size_t)row * D_ + t] = acc * il;
    }

    if (write_w) {
        float4* wrow = (float4*)(wts + (size_t)row * T_);
        float4 vals[4];
        bool   act[4];
        #pragma unroll
        for (int u = 0; u < 4; ++u) {
            int i = t + u * 128;           // 512 float4 per row
            act[u] = (i * 4 <= r);
            if (act[u]) vals[u] = __ldcs(wrow + i);
        }
        #pragma unroll
        for (int u = 0; u < 4; ++u) {
            int i = t + u * 128;
            float4 o = act[u]
                ? make_float4(vals[u].x * il, vals[u].y * il,
                              vals[u].z * il, vals[u].w * il)
                : make_float4(0.f, 0.f, 0.f, 0.f);
            __stcs(wrow + i, o);
        }
    }
}

extern "C" void kernel_launch(void* const* d_in, const int* in_sizes, int n_in,
                              void* d_out, int out_size)
{
    // reference signature order: q, v, k, q_mask, v_mask
    const float* q = (const float*)d_in[0];
    const float* v = (const float*)d_in[1];
    const float* k = (const float*)d_in[2];

    const size_t nW = (size_t)B_ * T_ * T_;
    const size_t nR = (size_t)B_ * T_ * D_;
    const int write_w = ((size_t)out_size >= nW + nR) ? 1 : 0;

    float* wts = (float*)d_out;
    float* res = (float*)d_out + ((size_t)out_size - nR);

    // lazily created on the first (uncaptured) correctness call; reused by
    // every subsequent call so the captured graph is identical each time.
    static cudaStream_t s2 = nullptr;
    static cudaEvent_t ev1 = nullptr, ev2 = nullptr;
    if (s2 == nullptr) {
        cudaStreamCreateWithFlags(&s2, cudaStreamNonBlocking);
        cudaEventCreateWithFlags(&ev1, cudaEventDisableTiming);
        cudaEventCreateWithFlags(&ev2, cudaEventDisableTiming);
    }

    cudaFuncSetAttribute(attn_mma, cudaFuncAttributeMaxDynamicSharedMemorySize, SMEM_TOTAL);

    dim3 pgrid(16 * 8, B_, 3);
    prep_kernel<<<pgrid, 256>>>(q, k, v);

    // big half: qt 16..31 -> 104 chunks/batch * 8 = 832 CTAs
    attn_mma<<<832, 128, SMEM_TOTAL>>>(wts, write_w, 16, 31);

    // fork: reduce of big rows (1024..2047) runs on s2 concurrently with
    // the small attn half on the main stream.
    cudaEventRecord(ev1, 0);
    cudaStreamWaitEvent(s2, ev1, 0);
    reduce_kernel<<<4096, 256, 0, s2>>>(wts, res, write_w, 1024);

    // small half: qt 0..15 -> 40 chunks/batch * 8 = 320 CTAs
    attn_mma<<<320, 128, SMEM_TOTAL>>>(wts, write_w, 0, 15);
    reduce_kernel<<<4096, 256>>>(wts, res, write_w, 0);

    // join
    cudaEventRecord(ev2, s2);
    cudaStreamWaitEvent(0, ev2, 0);
}

// round 16
// speedup vs baseline: 1.5146x; 1.0912x over previous
#include <cuda_runtime.h>
#include <cuda_bf16.h>
#include <cuda_fp16.h>
#include <cstdint>

// BaseDenseAttention — causal dense attention, fp32, B=8 T=2048 D=64.
// Outputs concatenated in d_out: weights [B,T,T], result [B,T,D].
// Round 14: occupancy push. R13 profile showed tensor pipe only ~25% active
// (dependency-stalled, 2 warps/SMSP). Fit 3 CTAs/SM:
//   - drop Q-fragment register cache (re-ldsm per ks) to cut regs 195->~160
//   - __launch_bounds__(128, 3) + max smem carveout (3 x 73728 B fits 228KB)
//   - serial 3-launch structure (prep -> attn qt0..31 -> reduce), no streams.
// Numerics unchanged: 3-term bf16 split S, fp16 PV + online max, split-K.

#define B_  8
#define T_  2048
#define D_  64
#define TM  64
#define TN  128
#define NQT 32                 // 64-row q tiles
#define CHUNK  2
#define NCTA   (144 * 8)       // 144 chunks per batch over qt 0..31

// scratch: partial row sums / partial O per (b,qt64,split<=8)
__device__ float g_pl[2048 * 64];
__device__ float g_pO[2048 * 64 * 64];

// pre-converted tiles: [tensor(3)][b(8)][tile128(16)][2 planes][128 x 144B]
// Q,K: plane0 = bf16 hi, plane1 = bf16 lo.  V: plane0 = fp16.
#define PITCH 144
#define PLANE 18432
#define QPLANE 9216
__device__ __align__(16) char g_cvt[3 * 8 * 16 * 2 * PLANE];

__device__ __forceinline__ char* cvt_plane(int t, int b, int tile) {
    return g_cvt + (size_t)(((t * 8 + b) * 16 + tile) * 2) * PLANE;
}

#define SM_QH 0
#define SM_KH (2 * QPLANE)
#define SM_VH (SM_KH + 2 * PLANE)
#define SMEM_TOTAL (SM_VH + PLANE)      // 73728 B

__device__ __forceinline__ uint32_t smem_u32(const void* p) {
    uint32_t a;
    asm("{ .reg .u64 t; cvta.to.shared.u64 t, %1; cvt.u32.u64 %0, t; }" : "=r"(a) : "l"(p));
    return a;
}
__device__ __forceinline__ void ldsm4(uint32_t addr, uint32_t* r) {
    asm volatile("ldmatrix.sync.aligned.m8n8.x4.shared.b16 {%0,%1,%2,%3}, [%4];"
                 : "=r"(r[0]), "=r"(r[1]), "=r"(r[2]), "=r"(r[3]) : "r"(addr));
}
__device__ __forceinline__ void ldsm4t(uint32_t addr, uint32_t* r) {
    asm volatile("ldmatrix.sync.aligned.m8n8.x4.trans.shared.b16 {%0,%1,%2,%3}, [%4];"
                 : "=r"(r[0]), "=r"(r[1]), "=r"(r[2]), "=r"(r[3]) : "r"(addr));
}
__device__ __forceinline__ void mma16816(float* d, const uint32_t* a, const uint32_t* b) {
    asm volatile("mma.sync.aligned.m16n8k16.row.col.f32.bf16.bf16.f32 "
                 "{%0,%1,%2,%3}, {%4,%5,%6,%7}, {%8,%9}, {%0,%1,%2,%3};"
                 : "+f"(d[0]), "+f"(d[1]), "+f"(d[2]), "+f"(d[3])
                 : "r"(a[0]), "r"(a[1]), "r"(a[2]), "r"(a[3]), "r"(b[0]), "r"(b[1]));
}
__device__ __forceinline__ void mma16816h(float* d, const uint32_t* a, const uint32_t* b) {
    asm volatile("mma.sync.aligned.m16n8k16.row.col.f32.f16.f16.f32 "
                 "{%0,%1,%2,%3}, {%4,%5,%6,%7}, {%8,%9}, {%0,%1,%2,%3};"
                 : "+f"(d[0]), "+f"(d[1]), "+f"(d[2]), "+f"(d[3])
                 : "r"(a[0]), "r"(a[1]), "r"(a[2]), "r"(a[3]), "r"(b[0]), "r"(b[1]));
}
__device__ __forceinline__ void cp16(uint32_t dst, const void* src) {
    asm volatile("cp.async.cg.shared.global [%0], [%1], 16;" :: "r"(dst), "l"(src));
}
#define CP_COMMIT() asm volatile("cp.async.commit_group;" ::: "memory")
#define CP_WAIT(N)  asm volatile("cp.async.wait_group %0;" :: "n"(N) : "memory")

__device__ __forceinline__ void cp_q(uint32_t dst, const char* srchi, int tid) {
    #pragma unroll
    for (int i = 0; i < 9; ++i) {
        int s = tid + i * 128;
        const char* src = (s < 576) ? (srchi + s * 16)
                                    : (srchi + PLANE + (s - 576) * 16);
        cp16(dst + s * 16, src);
    }
}
__device__ __forceinline__ void cp_k(uint32_t dst, const char* src, int tid) {
    #pragma unroll
    for (int i = 0; i < 18; ++i) {
        int o = (tid + i * 128) * 16;
        cp16(dst + o, src + o);
    }
}
__device__ __forceinline__ void cp_v(uint32_t dst, const char* src, int tid) {
    #pragma unroll
    for (int i = 0; i < 9; ++i) {
        int o = (tid + i * 128) * 16;
        cp16(dst + o, src + o);
    }
}

__device__ __forceinline__ void split2(float x, float y, uint32_t& hi, uint32_t& lo) {
    __nv_bfloat16 hx = __float2bfloat16_rn(x);
    __nv_bfloat16 hy = __float2bfloat16_rn(y);
    float rx = x - __bfloat162float(hx);
    float ry = y - __bfloat162float(hy);
    __nv_bfloat16 lx = __float2bfloat16_rn(rx);
    __nv_bfloat16 ly = __float2bfloat16_rn(ry);
    hi = ((uint32_t)__bfloat16_as_ushort(hy) << 16) | __bfloat16_as_ushort(hx);
    lo = ((uint32_t)__bfloat16_as_ushort(ly) << 16) | __bfloat16_as_ushort(lx);
}
__device__ __forceinline__ uint32_t pack_h2(float x, float y) {
    return ((uint32_t)__half_as_ushort(__float2half_rn(y)) << 16)
         | __half_as_ushort(__float2half_rn(x));
}

// big-first chunk schedule over [qlo, qhi]: full 2-tile chunks (qt desc),
// then 1-tile leftovers.
__device__ __forceinline__ void get_chunk(int cid, int qlo, int qhi,
                                          int& qt, int& sp) {
    int c = cid;
    for (int q = qhi; q >= qlo; --q) {
        int f = ((q >> 1) + 1) >> 1;
        if (c < f) { qt = q; sp = c; return; }
        c -= f;
    }
    for (int q = qhi; q >= qlo; --q) {
        int ntk = (q >> 1) + 1;
        if (ntk & 1) {
            if (c == 0) { qt = q; sp = ntk >> 1; return; }
            --c;
        }
    }
    qt = qlo; sp = 0;
}

// ---- prep: fp32 tiles -> bf16 hi/lo (Q,K) or fp16 (V) pitched planes ----
__global__ __launch_bounds__(256)
void prep_kernel(const float* __restrict__ q, const float* __restrict__ k,
                 const float* __restrict__ v)
{
    const int tile = blockIdx.x >> 3, qu = blockIdx.x & 7;   // 16 rows per CTA
    const int b = blockIdx.y, t = blockIdx.z;
    const int tid = threadIdx.x;
    const float* src = (t == 0 ? q : (t == 1 ? k : v))
                       + ((size_t)(b * T_ + tile * 128 + qu * 16)) * D_;
    char* dh = cvt_plane(t, b, tile) + qu * 16 * PITCH;
    char* dl = dh + PLANE;
    int row = tid >> 4, c4 = tid & 15;                       // 256 slots
    float4 x = *(const float4*)(src + row * D_ + c4 * 4);
    if (t < 2) {
        uint32_t h0, l0, h1, l1;
        split2(x.x, x.y, h0, l0);
        split2(x.z, x.w, h1, l1);
        *(uint2*)(dh + row * PITCH + c4 * 8) = make_uint2(h0, h1);
        *(uint2*)(dl + row * PITCH + c4 * 8) = make_uint2(l0, l1);
    } else {
        *(uint2*)(dh + row * PITCH + c4 * 8) =
            make_uint2(pack_h2(x.x, x.y), pack_h2(x.z, x.w));
    }
}

__global__ __launch_bounds__(128, 3)
void attn_mma(float* __restrict__ wts, int write_w, int qlo, int qhi)
{
    extern __shared__ char smem[];
    const uint32_t sb = smem_u32(smem);
    const int tid  = threadIdx.x;
    const int w    = tid >> 5;          // 0..3
    const int lane = tid & 31;
    const int gid  = lane >> 2;
    const int tig  = lane & 3;
    const int m    = lane >> 3;
    const int rL   = lane & 7;

    const int cid = blockIdx.x >> 3;
    const int b   = blockIdx.x & 7;
    int qt, sp;
    get_chunk(cid, qlo, qhi, qt, sp);
    const int ntk   = (qt >> 1) + 1;
    const int kt0   = sp * CHUNK;
    const int ktend = min(kt0 + CHUNK, ntk);
    const int dtile = qt >> 1;          // diagonal key-tile index
    const int chunkid = (b * NQT + qt) * 8 + sp;
    const int rloc  = w * 16 + gid;     // 0..63

    // Q source: 64-row half of the 128-row converted tile
    const char* qsrc = cvt_plane(0, b, qt >> 1) + (qt & 1) * 64 * PITCH;
    cp_q(sb + SM_QH, qsrc, tid);                        CP_COMMIT();
    cp_k(sb + SM_KH, cvt_plane(1, b, kt0), tid);        CP_COMMIT();
    cp_v(sb + SM_VH, cvt_plane(2, b, kt0), tid);        CP_COMMIT();

    const uint32_t a_row = (uint32_t)(w * 16 + (m & 1) * 8 + rL);
    const uint32_t a_mo  = (uint32_t)((m >> 1) * 16);
    const uint32_t b_ro  = (uint32_t)((m >> 1) * 8 + rL);
    const uint32_t b_mo  = (uint32_t)((m & 1) * 16);
    const uint32_t v_ro  = (uint32_t)((m & 1) * 8 + rL);
    const uint32_t v_mo  = (uint32_t)((m >> 1) * 16);

    float O[8][4];
    #pragma unroll
    for (int i = 0; i < 8; ++i)
        #pragma unroll
        for (int j = 0; j < 4; ++j) O[i][j] = 0.f;
    float sumA = 0.f, sumB = 0.f;
    float mA = -1e30f, mB = -1e30f;
    const int row0 = qt * TM + w * 16 + gid;

    for (int kt = kt0; kt < ktend; ++kt) {
        const int diag = (kt == dtile);
        const int havenext = (kt + 1 < ktend);

        CP_WAIT(1);          // Q + K(kt) resident (V may be in flight)
        __syncthreads();

        #pragma unroll
        for (int half = 0; half < 2; ++half) {
            // even-qt diagonal tile: upper 64-key half fully masked -> skip
            const bool skip = diag && (half == 1) && !(qt & 1);

            float S[8][4];
            if (!skip) {
                #pragma unroll
                for (int i = 0; i < 8; ++i)
                    #pragma unroll
                    for (int j = 0; j < 4; ++j) S[i][j] = 0.f;
                #pragma unroll
                for (int ks = 0; ks < 4; ++ks) {
                    uint32_t aH[4], aL[4];
                    uint32_t aaddr = a_row * PITCH + (uint32_t)(ks * 32) + a_mo;
                    ldsm4(sb + SM_QH + aaddr, aH);
                    ldsm4(sb + SM_QH + QPLANE + aaddr, aL);
                    #pragma unroll
                    for (int nbp = 0; nbp < 4; ++nbp) {
                        uint32_t bH[4], bL[4];
                        uint32_t krow = (uint32_t)(half * 64 + nbp * 16) + b_ro;
                        uint32_t kaddr = krow * PITCH + (uint32_t)(ks * 32) + b_mo;
                        ldsm4(sb + SM_KH + kaddr, bH);
                        ldsm4(sb + SM_KH + PLANE + kaddr, bL);
                        mma16816(S[2*nbp],   aH, bH);
                        mma16816(S[2*nbp],   aH, bL);
                        mma16816(S[2*nbp],   aL, bH);
                        mma16816(S[2*nbp+1], aH, bH + 2);
                        mma16816(S[2*nbp+1], aH, bL + 2);
                        mma16816(S[2*nbp+1], aL, bH + 2);
                    }
                }
            }

            if (half == 1) {
                __syncthreads();
                if (havenext) { cp_k(sb + SM_KH, cvt_plane(1, b, kt + 1), tid); }
                CP_COMMIT();
            }

            uint32_t E2[8][2];
            if (!skip) {
                // ---------- epilogue: mask, online max, exp, store E ----------
                const int colbase = kt * TN + half * 64;
                float mlA = -1e30f, mlB = -1e30f;
                #pragma unroll
                for (int nb = 0; nb < 8; ++nb) {
                    int c = colbase + nb * 8 + 2 * tig;
                    if (diag) {
                        if (c     > row0)     S[nb][0] = -1e30f;
                        if (c + 1 > row0)     S[nb][1] = -1e30f;
                        if (c     > row0 + 8) S[nb][2] = -1e30f;
                        if (c + 1 > row0 + 8) S[nb][3] = -1e30f;
                    }
                    mlA = fmaxf(mlA, fmaxf(S[nb][0], S[nb][1]));
                    mlB = fmaxf(mlB, fmaxf(S[nb][2], S[nb][3]));
                }
                mlA = fmaxf(mlA, __shfl_xor_sync(0xFFFFFFFFu, mlA, 1));
                mlA = fmaxf(mlA, __shfl_xor_sync(0xFFFFFFFFu, mlA, 2));
                mlB = fmaxf(mlB, __shfl_xor_sync(0xFFFFFFFFu, mlB, 1));
                mlB = fmaxf(mlB, __shfl_xor_sync(0xFFFFFFFFu, mlB, 2));
                {
                    float mAn = fmaxf(mA, mlA), mBn = fmaxf(mB, mlB);
                    float fA = __expf(mA - mAn), fB = __expf(mB - mBn);
                    mA = mAn; mB = mBn;
                    sumA *= fA; sumB *= fB;
                    #pragma unroll
                    for (int nd = 0; nd < 8; ++nd) {
                        O[nd][0] *= fA; O[nd][1] *= fA;
                        O[nd][2] *= fB; O[nd][3] *= fB;
                    }
                }
                const float emA = __expf(mA), emB = __expf(mB);
                #pragma unroll
                for (int nb = 0; nb < 8; ++nb) {
                    int c = colbase + nb * 8 + 2 * tig;
                    float e0 = __expf(S[nb][0] - mA);
                    float e1 = __expf(S[nb][1] - mA);
                    float e2 = __expf(S[nb][2] - mB);
                    float e3 = __expf(S[nb][3] - mB);
                    sumA += e0 + e1;
                    sumB += e2 + e3;
                    if (write_w) {
                        *(float2*)(wts + ((size_t)(b * T_ + row0))     * T_ + c) =
                            make_float2(e0 * emA, e1 * emA);
                        *(float2*)(wts + ((size_t)(b * T_ + row0 + 8)) * T_ + c) =
                            make_float2(e2 * emB, e3 * emB);
                    }
                    E2[nb][0] = pack_h2(e0, e1);
                    E2[nb][1] = pack_h2(e2, e3);
                }
            }

            if (half == 0) {
                CP_WAIT(0);
                __syncthreads();
            }

            if (!skip) {
                // ---------- O' += E' @ V (single fp16 term) ----------
                #pragma unroll
                for (int pks = 0; pks < 4; ++pks) {
                    uint32_t aP[4] = {E2[2*pks][0], E2[2*pks][1],
                                      E2[2*pks+1][0], E2[2*pks+1][1]};
                    #pragma unroll
                    for (int dbp = 0; dbp < 4; ++dbp) {
                        uint32_t bh[4];
                        uint32_t vrow = (uint32_t)(half * 64 + pks * 16) + v_ro;
                        uint32_t vaddr = vrow * PITCH + (uint32_t)(dbp * 32) + v_mo;
                        ldsm4t(sb + SM_VH + vaddr, bh);
                        mma16816h(O[2*dbp],   aP, bh);
                        mma16816h(O[2*dbp+1], aP, bh + 2);
                    }
                }
            }
        }

        __syncthreads();
        if (havenext) { cp_v(sb + SM_VH, cvt_plane(2, b, kt + 1), tid); }
        CP_COMMIT();
    }

    // ---------- write raw partials ----------
    sumA += __shfl_xor_sync(0xFFFFFFFFu, sumA, 1);
    sumA += __shfl_xor_sync(0xFFFFFFFFu, sumA, 2);
    sumB += __shfl_xor_sync(0xFFFFFFFFu, sumB, 1);
    sumB += __shfl_xor_sync(0xFFFFFFFFu, sumB, 2);
    const float emA = __expf(mA), emB = __expf(mB);
    if (tig == 0) {
        g_pl[chunkid * 64 + rloc]     = sumA * emA;
        g_pl[chunkid * 64 + rloc + 8] = sumB * emB;
    }
    #pragma unroll
    for (int nd = 0; nd < 8; ++nd) {
        int c = nd * 8 + 2 * tig;
        *(float2*)&g_pO[(size_t)chunkid * 4096 + rloc * 64 + c] =
            make_float2(O[nd][0] * emA, O[nd][1] * emA);
        *(float2*)&g_pO[(size_t)chunkid * 4096 + (rloc + 8) * 64 + c] =
            make_float2(O[nd][2] * emB, O[nd][3] * emB);
    }
}

// ---- reduce: combine partials, normalize lower triangle, zero upper ----
// 2 rows per 256-thr CTA.
__global__ __launch_bounds__(256)
void reduce_kernel(float* __restrict__ wts, float* __restrict__ res, int write_w)
{
    const int tid  = threadIdx.x;
    const int rsel = tid >> 7;             // 0/1
    const int t    = tid & 127;
    const int row  = blockIdx.x * 2 + rsel;
    const int b    = row >> 11;
    const int r    = row & (T_ - 1);
    const int qt   = r >> 6;               // 64-row tile
    const int rloc = r & 63;
    const int ntk  = (qt >> 1) + 1;
    const int ns   = (ntk + 1) >> 1;
    const int cb   = (b * NQT + qt) * 8;

    float l = 0.f;
    #pragma unroll 4
    for (int s = 0; s < ns; ++s) l += g_pl[(cb + s) * 64 + rloc];
    const float il = 1.f / l;

    if (t < 64) {
        float acc = 0.f;
        #pragma unroll 4
        for (int s = 0; s < ns; ++s)
            acc += g_pO[(size_t)(cb + s) * 4096 + rloc * 64 + t];
        res[(size_t)row * D_ + t] = acc * il;
    }

    if (write_w) {
        float4* wrow = (float4*)(wts + (size_t)row * T_);
        float4 vals[4];
        bool   act[4];
        #pragma unroll
        for (int u = 0; u < 4; ++u) {
            int i = t + u * 128;           // 512 float4 per row
            act[u] = (i * 4 <= r);
            if (act[u]) vals[u] = __ldcs(wrow + i);
        }
        #pragma unroll
        for (int u = 0; u < 4; ++u) {
            int i = t + u * 128;
            float4 o = act[u]
                ? make_float4(vals[u].x * il, vals[u].y * il,
                              vals[u].z * il, vals[u].w * il)
                : make_float4(0.f, 0.f, 0.f, 0.f);
            __stcs(wrow + i, o);
        }
    }
}

extern "C" void kernel_launch(void* const* d_in, const int* in_sizes, int n_in,
                              void* d_out, int out_size)
{
    // reference signature order: q, v, k, q_mask, v_mask
    const float* q = (const float*)d_in[0];
    const float* v = (const float*)d_in[1];
    const float* k = (const float*)d_in[2];

    const size_t nW = (size_t)B_ * T_ * T_;
    const size_t nR = (size_t)B_ * T_ * D_;
    const int write_w = ((size_t)out_size >= nW + nR) ? 1 : 0;

    float* wts = (float*)d_out;
    float* res = (float*)d_out + ((size_t)out_size - nR);

    cudaFuncSetAttribute(attn_mma, cudaFuncAttributeMaxDynamicSharedMemorySize, SMEM_TOTAL);
    cudaFuncSetAttribute(attn_mma, cudaFuncAttributePreferredSharedMemoryCarveout, 100);

    dim3 pgrid(16 * 8, B_, 3);
    prep_kernel<<<pgrid, 256>>>(q, k, v);
    attn_mma<<<NCTA, 128, SMEM_TOTAL>>>(wts, write_w, 0, 31);
    reduce_kernel<<<B_ * T_ / 2, 256>>>(wts, res, write_w);
}